// round 3
// baseline (speedup 1.0000x reference)
#include <cuda_runtime.h>
#include <math.h>

#define N_ENT 200000
#define N_USR 100000
#define DIM   64
#define E_N   1500000
#define NI_N  1000000
#define N_RELM1 10
#define HALF_D 32   // float2 lanes per row

// ---------------- device scratch (no allocation allowed) ----------------
__device__ int   g_remap[16];
__device__ int   g_cnt_ent[N_ENT];
__device__ int   g_off_ent[N_ENT + 1];
__device__ int   g_cnt_usr[N_USR];
__device__ int   g_off_usr[N_USR + 1];
__device__ int   g_packed[E_N];      // tail | (virt<<18)
__device__ int   g_items[NI_N];
__device__ int   g_part_ent[512];
__device__ int   g_part_usr[512];
__device__ float g_entB[N_ENT * DIM];
__device__ float g_usrB[N_USR * DIM];

// ---------------- helpers ----------------
__device__ __forceinline__ float wsum(float v) {
    #pragma unroll
    for (int o = 16; o > 0; o >>= 1) v += __shfl_xor_sync(0xffffffffu, v, o);
    return v;
}

// squash(acc/den) + base   (squash = (sq/(sq+1)) * u / max(||u||, eps))
__device__ __forceinline__ float2 squash_add(float2 acc, float den, float2 base) {
    float x = acc.x / den, y = acc.y / den;
    float sq = wsum(x * x + y * y);
    float nrm = sqrtf(sq);
    float s = (sq / (sq + 1.0f)) / fmaxf(nrm, 1e-12f);
    return make_float2(x * s + base.x, y * s + base.y);
}

// ---------------- preprocessing kernels ----------------
__global__ void remap_kernel(const float* __restrict__ relw,
                             const float* __restrict__ lat) {
    int r = threadIdx.x;
    if (r >= N_RELM1) return;
    float best = -1e30f; int bi = 0;
    for (int v = 0; v < 3; v++) {
        float s = 0.f;
        for (int k = 0; k < DIM; k++) s += relw[r * DIM + k] * lat[v * DIM + k];
        if (s > best) { best = s; bi = v; }
    }
    g_remap[r] = bi;
}

__global__ void zero_k(int* __restrict__ p, int n) {
    for (int i = blockIdx.x * blockDim.x + threadIdx.x; i < n; i += gridDim.x * blockDim.x)
        p[i] = 0;
}

__global__ void hist_k(const int* __restrict__ keys, int* __restrict__ cnt, int n) {
    for (int i = blockIdx.x * blockDim.x + threadIdx.x; i < n; i += gridDim.x * blockDim.x)
        atomicAdd(&cnt[keys[i]], 1);
}

__global__ void block_sums_k(const int* __restrict__ in, int* __restrict__ part, int n) {
    __shared__ int sh[1024];
    int g = blockIdx.x * 1024 + threadIdx.x;
    sh[threadIdx.x] = (g < n) ? in[g] : 0;
    __syncthreads();
    for (int d = 512; d > 0; d >>= 1) {
        if (threadIdx.x < d) sh[threadIdx.x] += sh[threadIdx.x + d];
        __syncthreads();
    }
    if (threadIdx.x == 0) part[blockIdx.x] = sh[0];
}

__global__ void scan_partials_k(int* __restrict__ p, int n) {
    __shared__ int sh[256];
    int v = (threadIdx.x < n) ? p[threadIdx.x] : 0;
    sh[threadIdx.x] = v;
    __syncthreads();
    for (int d = 1; d < 256; d <<= 1) {
        int t = (threadIdx.x >= d) ? sh[threadIdx.x - d] : 0;
        __syncthreads();
        sh[threadIdx.x] += t;
        __syncthreads();
    }
    if (threadIdx.x < n) p[threadIdx.x] = sh[threadIdx.x] - v;  // exclusive
}

__global__ void scan_write_k(const int* __restrict__ in, const int* __restrict__ part,
                             int* __restrict__ off, int n) {
    __shared__ int sh[1024];
    int g = blockIdx.x * 1024 + threadIdx.x;
    int v = (g < n) ? in[g] : 0;
    sh[threadIdx.x] = v;
    __syncthreads();
    for (int d = 1; d < 1024; d <<= 1) {
        int t = (threadIdx.x >= d) ? sh[threadIdx.x - d] : 0;
        __syncthreads();
        sh[threadIdx.x] += t;
        __syncthreads();
    }
    int base = part[blockIdx.x];
    if (g < n) off[g] = base + sh[threadIdx.x] - v;   // exclusive scan
    if (g == n - 1) off[n] = base + sh[threadIdx.x];  // total
}

__global__ void scatter_ent_k(const int* __restrict__ head, const int* __restrict__ tail,
                              const int* __restrict__ et, const int* __restrict__ off,
                              int* __restrict__ cur, int* __restrict__ packed, int n) {
    for (int i = blockIdx.x * blockDim.x + threadIdx.x; i < n; i += gridDim.x * blockDim.x) {
        int h = head[i];
        int pos = off[h] + atomicAdd(&cur[h], 1);
        int v = g_remap[et[i] - 1];
        packed[pos] = tail[i] | (v << 18);
    }
}

__global__ void scatter_usr_k(const int* __restrict__ uid, const int* __restrict__ iid,
                              const int* __restrict__ off, int* __restrict__ cur,
                              int* __restrict__ items, int n) {
    for (int i = blockIdx.x * blockDim.x + threadIdx.x; i < n; i += gridDim.x * blockDim.x) {
        int u = uid[i];
        int pos = off[u] + atomicAdd(&cur[u], 1);
        items[pos] = iid[i];
    }
}

// ---------------- main fused LWS kernels ----------------
// one warp per entity head: all 3 virtual relations, all 3 LWS iterations fused.
__global__ void __launch_bounds__(256)
entity_lws_k(const float2* __restrict__ ent_in, const float* __restrict__ aggw, int hop,
             const int* __restrict__ off, const int* __restrict__ packed,
             float2* __restrict__ store, float2* __restrict__ res) {
    int w = (blockIdx.x * blockDim.x + threadIdx.x) >> 5;
    if (w >= N_ENT) return;
    int lane = threadIdx.x & 31;

    float2 en = ent_in[w * HALF_D + lane];
    int s = off[w], e = off[w + 1];

    // softmax(agg_w[hop])
    float a0 = aggw[hop * 3 + 0], a1 = aggw[hop * 3 + 1], a2 = aggw[hop * 3 + 2];
    float mx = fmaxf(a0, fmaxf(a1, a2));
    float e0 = expf(a0 - mx), e1 = expf(a1 - mx), e2 = expf(a2 - mx);
    float inv = 1.0f / (e0 + e1 + e2);
    float w0 = e0 * inv, w1 = e1 * inv, w2 = e2 * inv;

    // ---- pass 0: plain per-virt mean ----
    float2 acc0 = {0, 0}, acc1 = {0, 0}, acc2 = {0, 0};
    int c0 = 0, c1 = 0, c2 = 0;
    for (int b = s; b < e; b += 32) {
        int m = min(32, e - b);
        int pk = (lane < m) ? packed[b + lane] : 0;
        for (int j = 0; j < m; j++) {
            int p = __shfl_sync(0xffffffffu, pk, j);
            int t = p & 0x3FFFF, v = p >> 18;
            float2 nt = ent_in[t * HALF_D + lane];
            if (v == 0)      { acc0.x += nt.x; acc0.y += nt.y; c0++; }
            else if (v == 1) { acc1.x += nt.x; acc1.y += nt.y; c1++; }
            else             { acc2.x += nt.x; acc2.y += nt.y; c2++; }
        }
    }
    float d0 = fmaxf((float)c0, 1.f), d1 = fmaxf((float)c1, 1.f), d2 = fmaxf((float)c2, 1.f);
    float2 u10 = squash_add(acc0, d0, en);
    float2 u11 = squash_add(acc1, d1, en);
    float2 u12 = squash_add(acc2, d2, en);

    // ---- pass 1: sim-weighted ----
    acc0 = make_float2(0, 0); acc1 = make_float2(0, 0); acc2 = make_float2(0, 0);
    for (int b = s; b < e; b += 32) {
        int m = min(32, e - b);
        int pk = (lane < m) ? packed[b + lane] : 0;
        for (int j = 0; j < m; j++) {
            int p = __shfl_sync(0xffffffffu, pk, j);
            int t = p & 0x3FFFF, v = p >> 18;
            float2 nt = ent_in[t * HALF_D + lane];
            float2 uv = (v == 0) ? u10 : ((v == 1) ? u11 : u12);
            float d = wsum(uv.x * nt.x + uv.y * nt.y);
            if (v == 0)      { acc0.x += d * nt.x; acc0.y += d * nt.y; }
            else if (v == 1) { acc1.x += d * nt.x; acc1.y += d * nt.y; }
            else             { acc2.x += d * nt.x; acc2.y += d * nt.y; }
        }
    }
    float2 u20 = squash_add(acc0, d0, en);
    float2 u21 = squash_add(acc1, d1, en);
    float2 u22 = squash_add(acc2, d2, en);

    // ---- pass 2: cumulative sim (d1^2 * d2), no squash ----
    acc0 = make_float2(0, 0); acc1 = make_float2(0, 0); acc2 = make_float2(0, 0);
    for (int b = s; b < e; b += 32) {
        int m = min(32, e - b);
        int pk = (lane < m) ? packed[b + lane] : 0;
        for (int j = 0; j < m; j++) {
            int p = __shfl_sync(0xffffffffu, pk, j);
            int t = p & 0x3FFFF, v = p >> 18;
            float2 nt = ent_in[t * HALF_D + lane];
            float2 uA = (v == 0) ? u10 : ((v == 1) ? u11 : u12);
            float2 uB = (v == 0) ? u20 : ((v == 1) ? u21 : u22);
            float pa = uA.x * nt.x + uA.y * nt.y;
            float pb = uB.x * nt.x + uB.y * nt.y;
            #pragma unroll
            for (int o = 16; o > 0; o >>= 1) {
                pa += __shfl_xor_sync(0xffffffffu, pa, o);
                pb += __shfl_xor_sync(0xffffffffu, pb, o);
            }
            float sc = pa * pa * pb;
            if (v == 0)      { acc0.x += sc * nt.x; acc0.y += sc * nt.y; }
            else if (v == 1) { acc1.x += sc * nt.x; acc1.y += sc * nt.y; }
            else             { acc2.x += sc * nt.x; acc2.y += sc * nt.y; }
        }
    }
    float2 u30 = make_float2(acc0.x / d0 + en.x, acc0.y / d0 + en.y);
    float2 u31 = make_float2(acc1.x / d1 + en.x, acc1.y / d1 + en.y);
    float2 u32 = make_float2(acc2.x / d2 + en.x, acc2.y / d2 + en.y);

    // weighted agg + l2norm + residual into d_out
    float2 ag = make_float2(w0 * u30.x + w1 * u31.x + w2 * u32.x,
                            w0 * u30.y + w1 * u31.y + w2 * u32.y);
    float sq = wsum(ag.x * ag.x + ag.y * ag.y);
    float in2 = 1.0f / fmaxf(sqrtf(sq), 1e-12f);
    float2 o = make_float2(ag.x * in2, ag.y * in2);
    if (store) store[w * HALF_D + lane] = o;
    float2 r = res[w * HALF_D + lane];
    r.x += o.x; r.y += o.y;
    res[w * HALF_D + lane] = r;
}

// one warp per user: 3 LWS iterations fused (neigh re-gathered fresh each iter).
__global__ void __launch_bounds__(256)
user_lws_k(const float2* __restrict__ ent_in, const float2* __restrict__ usr_in,
           const int* __restrict__ off, const int* __restrict__ items,
           float2* __restrict__ store, float2* __restrict__ res) {
    int w = (blockIdx.x * blockDim.x + threadIdx.x) >> 5;
    if (w >= N_USR) return;
    int lane = threadIdx.x & 31;

    float2 un = usr_in[w * HALF_D + lane];
    int s = off[w], e = off[w + 1];
    float den = fmaxf((float)(e - s), 1.f);

    // it0
    float2 acc = {0, 0};
    for (int b = s; b < e; b += 32) {
        int m = min(32, e - b);
        int it = (lane < m) ? items[b + lane] : 0;
        for (int j = 0; j < m; j++) {
            int t = __shfl_sync(0xffffffffu, it, j);
            float2 nt = ent_in[t * HALF_D + lane];
            acc.x += nt.x; acc.y += nt.y;
        }
    }
    float2 u1 = squash_add(acc, den, un);

    // it1
    acc = make_float2(0, 0);
    for (int b = s; b < e; b += 32) {
        int m = min(32, e - b);
        int it = (lane < m) ? items[b + lane] : 0;
        for (int j = 0; j < m; j++) {
            int t = __shfl_sync(0xffffffffu, it, j);
            float2 nt = ent_in[t * HALF_D + lane];
            float d = wsum(u1.x * nt.x + u1.y * nt.y);
            acc.x += d * nt.x; acc.y += d * nt.y;
        }
    }
    float2 u2 = squash_add(acc, den, un);

    // it2 (no squash)
    acc = make_float2(0, 0);
    for (int b = s; b < e; b += 32) {
        int m = min(32, e - b);
        int it = (lane < m) ? items[b + lane] : 0;
        for (int j = 0; j < m; j++) {
            int t = __shfl_sync(0xffffffffu, it, j);
            float2 nt = ent_in[t * HALF_D + lane];
            float d = wsum(u2.x * nt.x + u2.y * nt.y);
            acc.x += d * nt.x; acc.y += d * nt.y;
        }
    }
    float2 u3 = make_float2(acc.x / den + un.x, acc.y / den + un.y);

    float sq = wsum(u3.x * u3.x + u3.y * u3.y);
    float in2 = 1.0f / fmaxf(sqrtf(sq), 1e-12f);
    float2 o = make_float2(u3.x * in2, u3.y * in2);
    if (store) store[w * HALF_D + lane] = o;
    float2 r = res[w * HALF_D + lane];
    r.x += o.x; r.y += o.y;
    res[w * HALF_D + lane] = r;
}

// ---------------- launch ----------------
extern "C" void kernel_launch(void* const* d_in, const int* in_sizes, int n_in,
                              void* d_out, int out_size) {
    const float* entity_emb = (const float*)d_in[0];
    const float* user_emb   = (const float*)d_in[1];
    const float* latent     = (const float*)d_in[2];
    const float* relw       = (const float*)d_in[3];
    const float* aggw       = (const float*)d_in[4];
    const int*   eidx       = (const int*)d_in[5];   // [2,E] row-major: head, then tail
    const int*   etype      = (const int*)d_in[6];
    const int*   uidx       = (const int*)d_in[7];
    const int*   iidx       = (const int*)d_in[8];
    float* out = (float*)d_out;

    int *p_cnt_ent, *p_off_ent, *p_cnt_usr, *p_off_usr, *p_packed, *p_items, *p_pe, *p_pu;
    float *p_entB, *p_usrB;
    cudaGetSymbolAddress((void**)&p_cnt_ent, g_cnt_ent);
    cudaGetSymbolAddress((void**)&p_off_ent, g_off_ent);
    cudaGetSymbolAddress((void**)&p_cnt_usr, g_cnt_usr);
    cudaGetSymbolAddress((void**)&p_off_usr, g_off_usr);
    cudaGetSymbolAddress((void**)&p_packed,  g_packed);
    cudaGetSymbolAddress((void**)&p_items,   g_items);
    cudaGetSymbolAddress((void**)&p_pe,      g_part_ent);
    cudaGetSymbolAddress((void**)&p_pu,      g_part_usr);
    cudaGetSymbolAddress((void**)&p_entB,    g_entB);
    cudaGetSymbolAddress((void**)&p_usrB,    g_usrB);

    // init residual accumulators in d_out
    cudaMemcpyAsync(out, entity_emb, (size_t)N_ENT * DIM * sizeof(float), cudaMemcpyDeviceToDevice);
    cudaMemcpyAsync(out + (size_t)N_ENT * DIM, user_emb, (size_t)N_USR * DIM * sizeof(float),
                    cudaMemcpyDeviceToDevice);

    remap_kernel<<<1, 32>>>(relw, latent);

    zero_k<<<(N_ENT + 1023) / 1024, 1024>>>(p_cnt_ent, N_ENT);
    zero_k<<<(N_USR + 1023) / 1024, 1024>>>(p_cnt_usr, N_USR);

    hist_k<<<1024, 256>>>(eidx, p_cnt_ent, E_N);       // heads
    hist_k<<<1024, 256>>>(uidx, p_cnt_usr, NI_N);

    const int NB_E = (N_ENT + 1023) / 1024;  // 196
    const int NB_U = (N_USR + 1023) / 1024;  // 98
    block_sums_k<<<NB_E, 1024>>>(p_cnt_ent, p_pe, N_ENT);
    scan_partials_k<<<1, 256>>>(p_pe, NB_E);
    scan_write_k<<<NB_E, 1024>>>(p_cnt_ent, p_pe, p_off_ent, N_ENT);
    block_sums_k<<<NB_U, 1024>>>(p_cnt_usr, p_pu, N_USR);
    scan_partials_k<<<1, 256>>>(p_pu, NB_U);
    scan_write_k<<<NB_U, 1024>>>(p_cnt_usr, p_pu, p_off_usr, N_USR);

    zero_k<<<(N_ENT + 1023) / 1024, 1024>>>(p_cnt_ent, N_ENT);
    zero_k<<<(N_USR + 1023) / 1024, 1024>>>(p_cnt_usr, N_USR);

    scatter_ent_k<<<2048, 256>>>(eidx, eidx + E_N, etype, p_off_ent, p_cnt_ent, p_packed, E_N);
    scatter_usr_k<<<2048, 256>>>(uidx, iidx, p_off_usr, p_cnt_usr, p_items, NI_N);

    const int EB = (N_ENT * 32 + 255) / 256;   // 25000 blocks, warp per head
    const int UB = (N_USR * 32 + 255) / 256;   // 12500 blocks

    // hop 0: ent = entity_emb, usr = user_emb
    entity_lws_k<<<EB, 256>>>((const float2*)entity_emb, aggw, 0, p_off_ent, p_packed,
                              (float2*)p_entB, (float2*)out);
    user_lws_k<<<UB, 256>>>((const float2*)entity_emb, (const float2*)user_emb,
                            p_off_usr, p_items, (float2*)p_usrB,
                            (float2*)(out + (size_t)N_ENT * DIM));

    // hop 1: ent = g_entB, usr = g_usrB; outputs only feed residual
    entity_lws_k<<<EB, 256>>>((const float2*)p_entB, aggw, 1, p_off_ent, p_packed,
                              nullptr, (float2*)out);
    user_lws_k<<<UB, 256>>>((const float2*)p_entB, (const float2*)p_usrB,
                            p_off_usr, p_items, nullptr,
                            (float2*)(out + (size_t)N_ENT * DIM));
}